// round 14
// baseline (speedup 1.0000x reference)
#include <cuda_runtime.h>
#include <cuda_fp16.h>
#include <cuda_bf16.h>
#include <mma.h>
#include <cstdint>

using namespace nvcuda;

// GCN encoder: 2x GCNConv(relu) + fused mu/logvar GCNConv heads.
//   deg -> [reduce+dis] -> [tf32 wmma gemm1 (TMA-bulk staged), idx 3] -> scan -> CSR ->
//   per layer: [tf32 wmma GEMM, per-row cp.async.bulk staging -> g fp16] ->
//              [AGG pull: half-warp/edge uint2, 8 edges in flight, fp32 accum]
// h fp32, g fp16. No fp32 atomics anywhere; CSR rebuilt every launch.

#define NMAX 100000
#define EMAX 1600000
#define SCAN_B 1024

__device__ __align__(16) __half g_buf[(size_t)NMAX * 64];   // fp16 gather buffer
__device__ __align__(16) float  h_buf[(size_t)NMAX * 64];   // fp32 activations
__device__ float dis_buf[NMAX];
__device__ int   deg_buf[NMAX];
__device__ int   offs_buf[NMAX + 1];
__device__ int   cursor_buf[NMAX];
__device__ int   csr_buf[EMAX];
__device__ int   block_sums[128];

// ---------------------------------------------------------------------------
__device__ __forceinline__ uint32_t smem_u32(const void* p) {
    uint32_t a;
    asm("{ .reg .u64 t; cvta.to.shared.u64 t, %1; cvt.u32.u64 %0, t; }"
        : "=r"(a) : "l"(p));
    return a;
}

__device__ __forceinline__ void bulk_g2s(uint32_t dst, const void* src,
                                         uint32_t bytes, uint32_t mbar) {
    asm volatile(
        "cp.async.bulk.shared::cta.global.mbarrier::complete_tx::bytes [%0], [%1], %2, [%3];"
        :: "r"(dst), "l"(src), "r"(bytes), "r"(mbar) : "memory");
}

__device__ __forceinline__ void mbar_init(uint32_t mbar, uint32_t count) {
    asm volatile("mbarrier.init.shared.b64 [%0], %1;" :: "r"(mbar), "r"(count) : "memory");
}

__device__ __forceinline__ void mbar_expect_tx(uint32_t mbar, uint32_t bytes) {
    asm volatile("mbarrier.arrive.expect_tx.shared.b64 _, [%0], %1;"
                 :: "r"(mbar), "r"(bytes) : "memory");
}

__device__ __forceinline__ void mbar_wait(uint32_t mbar, uint32_t parity) {
    asm volatile(
        "{\n\t"
        ".reg .pred P1;\n\t"
        "WAIT_LOOP_%=:\n\t"
        "mbarrier.try_wait.parity.acquire.cta.shared::cta.b64 P1, [%0], %1, 0x989680;\n\t"
        "@P1 bra.uni WAIT_DONE_%=;\n\t"
        "bra.uni WAIT_LOOP_%=;\n\t"
        "WAIT_DONE_%=:\n\t"
        "}"
        :: "r"(mbar), "r"(parity) : "memory");
}

// ---------------------------------------------------------------------------
__global__ void zero_deg_kernel(int N) {
    int i = blockIdx.x * blockDim.x + threadIdx.x;
    if (i < N) deg_buf[i] = 0;
}

__global__ void count_deg_kernel(const int* __restrict__ ei, int E) {
    int e = blockIdx.x * blockDim.x + threadIdx.x;
    if (e < E) atomicAdd(&deg_buf[ei[E + e]], 1);
}

// Phase 1 of scan + fused dis = rsqrt(deg+1).
__global__ void reduce_deg_kernel(int N) {
    int idx = blockIdx.x * SCAN_B + threadIdx.x;
    int v = (idx < N) ? deg_buf[idx] : 0;
    if (idx < N) dis_buf[idx] = rsqrtf((float)v + 1.0f);
    int s = v;
    #pragma unroll
    for (int o = 16; o; o >>= 1) s += __shfl_down_sync(0xffffffffu, s, o);
    __shared__ int ws[32];
    int lane = threadIdx.x & 31, w = threadIdx.x >> 5;
    if (lane == 0) ws[w] = s;
    __syncthreads();
    if (w == 0) {
        int t = ws[lane];
        #pragma unroll
        for (int o = 16; o; o >>= 1) t += __shfl_down_sync(0xffffffffu, t, o);
        if (lane == 0) block_sums[blockIdx.x] = t;
    }
}

__global__ void scan_sums_kernel(int nb, int N) {
    int tid = threadIdx.x;
    __shared__ int sh[128];
    int v = (tid < nb) ? block_sums[tid] : 0;
    sh[tid] = v;
    __syncthreads();
    #pragma unroll
    for (int o = 1; o < 128; o <<= 1) {
        int t = (tid >= o) ? sh[tid - o] : 0;
        __syncthreads();
        sh[tid] += t;
        __syncthreads();
    }
    if (tid < nb) block_sums[tid] = sh[tid] - v;   // exclusive
    if (tid == 0) offs_buf[N] = sh[127];
}

__global__ void scan_deg_kernel(int N) {
    int idx = blockIdx.x * SCAN_B + threadIdx.x;
    int v = (idx < N) ? deg_buf[idx] : 0;
    int lane = threadIdx.x & 31, w = threadIdx.x >> 5;
    int s = v;
    #pragma unroll
    for (int o = 1; o < 32; o <<= 1) {
        int t = __shfl_up_sync(0xffffffffu, s, o);
        if (lane >= o) s += t;
    }
    __shared__ int ws[32];
    if (lane == 31) ws[w] = s;
    __syncthreads();
    if (w == 0) {
        int t = ws[lane];
        #pragma unroll
        for (int o = 1; o < 32; o <<= 1) {
            int u = __shfl_up_sync(0xffffffffu, t, o);
            if (lane >= o) t += u;
        }
        ws[lane] = t;
    }
    __syncthreads();
    int excl = s - v + (w > 0 ? ws[w - 1] : 0) + block_sums[blockIdx.x];
    if (idx < N) {
        offs_buf[idx]   = excl;
        cursor_buf[idx] = excl;
    }
}

__global__ void fill_csr_kernel(const int* __restrict__ ei, int E) {
    int e = blockIdx.x * blockDim.x + threadIdx.x;
    if (e < E) {
        int dst = ei[E + e];
        int p = atomicAdd(&cursor_buf[dst], 1);
        csr_buf[p] = ei[e];  // src
    }
}

// ---------------------------------------------------------------------------
// tf32 WMMA GEMM + row-scale: out[i, 0:64] = half((X[i,:] @ W) * dis[i])
// 128 rows x 64 cols per block, 256 threads (8 warps), warp = 16 rows x 64 cols.
// Staging via per-row cp.async.bulk (1 instr/thread) into padded smem rows.
#define WS_F 68   // Wh row stride (floats): 64 + 4 pad (272B)
#define ST_S 68   // Stg row stride (floats)

template <int K, bool COMBINED>
__global__ void __launch_bounds__(256)
gemm_wmma_kernel(const float* __restrict__ X,
                 const float* __restrict__ Wa,
                 const float* __restrict__ Wb,
                 __half* __restrict__ out, int N)
{
    constexpr int XS = K + 4;                 // Xh row stride (floats), 16B multiple
    extern __shared__ __align__(16) char sraw[];
    float* Xh = (float*)sraw;                         // 128 * XS floats
    float* Wh = (float*)(sraw + 128 * XS * 4);        // K * WS_F floats
    float* Stg = (float*)sraw;                        // aliases Xh (post-MMA)
    uint64_t* mbar_p = (uint64_t*)(sraw + 128 * XS * 4 + K * WS_F * 4);
    uint32_t mbar = smem_u32(mbar_p);

    int tid  = threadIdx.x;
    int warp = tid >> 5;
    int row0 = blockIdx.x * 128;

    if (tid == 0) mbar_init(mbar, 1);
    __syncthreads();
    if (tid == 0) mbar_expect_tx(mbar, 128 * K * 4 + K * 256);
    __syncthreads();

    // X: one 4K-byte row per thread (threads 0..127)
    if (tid < 128) {
        int gr = row0 + tid; if (gr >= N) gr = N - 1;
        bulk_g2s(smem_u32(&Xh[tid * XS]), X + (size_t)gr * K, K * 4, mbar);
    } else if (tid < 128 + K) {
        int k = tid - 128;
        if (COMBINED) {
            bulk_g2s(smem_u32(&Wh[k * WS_F]),      Wa + k * 32, 128, mbar);
            bulk_g2s(smem_u32(&Wh[k * WS_F + 32]), Wb + k * 32, 128, mbar);
        } else {
            bulk_g2s(smem_u32(&Wh[k * WS_F]),      Wa + k * 64, 256, mbar);
        }
    }
    mbar_wait(mbar, 0);

    // ---- barrier-free tf32 K loop: K/8 ksteps x 4 col-tiles ----
    wmma::fragment<wmma::accumulator, 16, 16, 8, float> acc[4];
    #pragma unroll
    for (int c = 0; c < 4; c++) wmma::fill_fragment(acc[c], 0.0f);

    #pragma unroll
    for (int ks = 0; ks < K / 8; ks++) {
        wmma::fragment<wmma::matrix_a, 16, 16, 8, wmma::precision::tf32, wmma::row_major> af;
        wmma::load_matrix_sync(af, &Xh[(warp * 16) * XS + ks * 8], XS);
        #pragma unroll
        for (int t = 0; t < af.num_elements; t++) af.x[t] = wmma::__float_to_tf32(af.x[t]);
        #pragma unroll
        for (int c = 0; c < 4; c++) {
            wmma::fragment<wmma::matrix_b, 16, 16, 8, wmma::precision::tf32, wmma::row_major> bf;
            wmma::load_matrix_sync(bf, &Wh[(ks * 8) * WS_F + c * 16], WS_F);
            #pragma unroll
            for (int t = 0; t < bf.num_elements; t++) bf.x[t] = wmma::__float_to_tf32(bf.x[t]);
            wmma::mma_sync(acc[c], af, bf, acc[c]);
        }
    }
    __syncthreads();   // all warps done reading Xh before Stg alias overwrite

    #pragma unroll
    for (int c = 0; c < 4; c++)
        wmma::store_matrix_sync(&Stg[(warp * 16) * ST_S + c * 16], acc[c], ST_S,
                                wmma::mem_row_major);
    __syncthreads();

    // epilogue: scale by dis, convert to fp16, STG.128
    {
        int r = tid >> 1, hsel = tid & 1;
        int gr = row0 + r;
        if (gr < N) {
            float d = dis_buf[gr];
            const float* src = &Stg[r * ST_S + hsel * 32];
            __half* dst = out + (size_t)gr * 64 + hsel * 32;
            #pragma unroll
            for (int c8 = 0; c8 < 4; c8++) {
                float4 u = *(const float4*)(src + c8 * 8);
                float4 v = *(const float4*)(src + c8 * 8 + 4);
                __half2 p0 = __float22half2_rn(make_float2(u.x * d, u.y * d));
                __half2 p1 = __float22half2_rn(make_float2(u.z * d, u.w * d));
                __half2 p2 = __float22half2_rn(make_float2(v.x * d, v.y * d));
                __half2 p3 = __float22half2_rn(make_float2(v.z * d, v.w * d));
                uint4 pk;
                pk.x = *(unsigned*)&p0;
                pk.y = *(unsigned*)&p1;
                pk.z = *(unsigned*)&p2;
                pk.w = *(unsigned*)&p3;
                *(uint4*)(dst + c8 * 8) = pk;
            }
        }
    }
}

// ---------------------------------------------------------------------------
// Pull aggregation: one warp per dst node. Half-warp (16 lanes x uint2 = 128B
// = one cache line) covers one edge's fp16 row; 8 edges in flight per warp.
__device__ __forceinline__ float4 h4_to_f4(uint2 v) {
    __half2 a = *(__half2*)&v.x;
    __half2 b = *(__half2*)&v.y;
    float2 fa = __half22float2(a);
    float2 fb = __half22float2(b);
    return make_float4(fa.x, fa.y, fb.x, fb.y);
}

// SPLIT: final fp32 mu/logvar. Otherwise fp32 h (64 cols).
template <bool RELU, bool SPLIT>
__global__ void agg_kernel(const __half* __restrict__ g,
                           const float* __restrict__ ba,
                           const float* __restrict__ bb,
                           float* __restrict__ out, int N)
{
    int warp = (int)((blockIdx.x * (unsigned)blockDim.x + threadIdx.x) >> 5);
    int lane = threadIdx.x & 31;
    if (warp >= N) return;
    int row  = warp;
    int half = lane >> 4;
    int li   = lane & 15;

    const uint2* gp = (const uint2*)g;   // 16 uint2 (64 halves) per row

    float4 a0 = make_float4(0.f, 0.f, 0.f, 0.f);
    float4 a1 = a0, a2 = a0, a3 = a0;
    if (half == 0) {
        float4 v = h4_to_f4(gp[(size_t)row * 16 + li]);   // self-loop term
        a0.x += v.x; a0.y += v.y; a0.z += v.z; a0.w += v.w;
    }

    int beg = offs_buf[row];
    int end = offs_buf[row + 1];
    int e = beg;
    for (; e + 7 < end; e += 8) {
        int s0 = csr_buf[e     + half];
        int s1 = csr_buf[e + 2 + half];
        int s2 = csr_buf[e + 4 + half];
        int s3 = csr_buf[e + 6 + half];
        float4 v0 = h4_to_f4(gp[(size_t)s0 * 16 + li]);
        float4 v1 = h4_to_f4(gp[(size_t)s1 * 16 + li]);
        float4 v2 = h4_to_f4(gp[(size_t)s2 * 16 + li]);
        float4 v3 = h4_to_f4(gp[(size_t)s3 * 16 + li]);
        a0.x += v0.x; a0.y += v0.y; a0.z += v0.z; a0.w += v0.w;
        a1.x += v1.x; a1.y += v1.y; a1.z += v1.z; a1.w += v1.w;
        a2.x += v2.x; a2.y += v2.y; a2.z += v2.z; a2.w += v2.w;
        a3.x += v3.x; a3.y += v3.y; a3.z += v3.z; a3.w += v3.w;
    }
    for (; e + 1 < end; e += 2) {
        int s = csr_buf[e + half];
        float4 v = h4_to_f4(gp[(size_t)s * 16 + li]);
        a0.x += v.x; a0.y += v.y; a0.z += v.z; a0.w += v.w;
    }
    if (e < end && half == 0) {
        float4 v = h4_to_f4(gp[(size_t)csr_buf[e] * 16 + li]);
        a0.x += v.x; a0.y += v.y; a0.z += v.z; a0.w += v.w;
    }
    a0.x += a1.x + a2.x + a3.x;
    a0.y += a1.y + a2.y + a3.y;
    a0.z += a1.z + a2.z + a3.z;
    a0.w += a1.w + a2.w + a3.w;

    a0.x += __shfl_xor_sync(0xffffffffu, a0.x, 16);
    a0.y += __shfl_xor_sync(0xffffffffu, a0.y, 16);
    a0.z += __shfl_xor_sync(0xffffffffu, a0.z, 16);
    a0.w += __shfl_xor_sync(0xffffffffu, a0.w, 16);

    if (half == 0) {
        float d = dis_buf[row];
        int c0 = 4 * li;
        float4 b4;
        if (SPLIT) {
            b4.x = (c0     < 32) ? ba[c0]     : bb[c0 - 32];
            b4.y = (c0 + 1 < 32) ? ba[c0 + 1] : bb[c0 + 1 - 32];
            b4.z = (c0 + 2 < 32) ? ba[c0 + 2] : bb[c0 + 2 - 32];
            b4.w = (c0 + 3 < 32) ? ba[c0 + 3] : bb[c0 + 3 - 32];
        } else {
            b4 = *(const float4*)(ba + c0);
        }
        float4 r;
        r.x = fmaf(d, a0.x, b4.x);
        r.y = fmaf(d, a0.y, b4.y);
        r.z = fmaf(d, a0.z, b4.z);
        r.w = fmaf(d, a0.w, b4.w);
        if (RELU) {
            r.x = fmaxf(r.x, 0.f); r.y = fmaxf(r.y, 0.f);
            r.z = fmaxf(r.z, 0.f); r.w = fmaxf(r.w, 0.f);
        }
        if (SPLIT) {
            if (li < 8) ((float4*)out)[(size_t)row * 8 + li] = r;                          // mu
            else        ((float4*)(out + (size_t)N * 32))[(size_t)row * 8 + (li - 8)] = r; // logvar
        } else {
            ((float4*)out)[(size_t)row * 16 + li] = r;
        }
    }
}

// ---------------------------------------------------------------------------
extern "C" void kernel_launch(void* const* d_in, const int* in_sizes, int n_in,
                              void* d_out, int out_size)
{
    const float* x   = (const float*)d_in[0];
    const int*   ei  = (const int*)  d_in[1];
    const float* W1  = (const float*)d_in[2];
    const float* b1  = (const float*)d_in[3];
    const float* W2  = (const float*)d_in[4];
    const float* b2  = (const float*)d_in[5];
    const float* Wmu = (const float*)d_in[6];
    const float* bmu = (const float*)d_in[7];
    const float* Wlv = (const float*)d_in[8];
    const float* blv = (const float*)d_in[9];
    float* out = (float*)d_out;

    int N = in_sizes[0] / 128;
    int E = in_sizes[1] / 2;
    int nb = (N + SCAN_B - 1) / SCAN_B;

    __half* g = nullptr;
    float*  h = nullptr;
    cudaGetSymbolAddress((void**)&g, g_buf);
    cudaGetSymbolAddress((void**)&h, h_buf);

    int gemm_grid = (N + 127) / 128;
    int agg_grid  = (N + 7) / 8;

    // smem: Xh + Wh + mbar (Stg aliases Xh; Xh >= Stg in both configs)
    const int smem128 = 128 * (128 + 4) * 4 + 128 * WS_F * 4 + 16;   // 102416
    const int smem64  = 128 * (64 + 4) * 4 + 64 * WS_F * 4 + 16;     //  52240

    cudaFuncSetAttribute(gemm_wmma_kernel<128, false>,
                         cudaFuncAttributeMaxDynamicSharedMemorySize, smem128);
    cudaFuncSetAttribute(gemm_wmma_kernel<64, false>,
                         cudaFuncAttributeMaxDynamicSharedMemorySize, smem64);
    cudaFuncSetAttribute(gemm_wmma_kernel<64, true>,
                         cudaFuncAttributeMaxDynamicSharedMemorySize, smem64);

    zero_deg_kernel<<<(N + 255) / 256, 256>>>(N);                                // idx 0
    count_deg_kernel<<<(E + 255) / 256, 256>>>(ei, E);                           // idx 1
    reduce_deg_kernel<<<nb, SCAN_B>>>(N);                                        // idx 2 (also dis)
    gemm_wmma_kernel<128, false><<<gemm_grid, 256, smem128>>>(x, W1, nullptr, g, N); // idx 3
    scan_sums_kernel<<<1, 128>>>(nb, N);
    scan_deg_kernel<<<nb, SCAN_B>>>(N);
    fill_csr_kernel<<<(E + 255) / 256, 256>>>(ei, E);

    agg_kernel<true, false><<<agg_grid, 256>>>(g, b1, nullptr, h, N);

    gemm_wmma_kernel<64, false><<<gemm_grid, 256, smem64>>>(h, W2, nullptr, g, N);
    agg_kernel<true, false><<<agg_grid, 256>>>(g, b2, nullptr, h, N);

    gemm_wmma_kernel<64, true><<<gemm_grid, 256, smem64>>>(h, Wmu, Wlv, g, N);
    agg_kernel<false, true><<<agg_grid, 256>>>(g, bmu, blv, out, N);
}

// round 15
// speedup vs baseline: 1.1279x; 1.1279x over previous
#include <cuda_runtime.h>
#include <cuda_fp16.h>
#include <cuda_bf16.h>
#include <mma.h>

using namespace nvcuda;

// GCN encoder: 2x GCNConv(relu) + fused mu/logvar GCNConv heads.
//   [prep: zero deg + convert all W to fp16] -> count -> [reduce+dis] ->
//   [wmma gemm1, idx 3] -> scan -> CSR fill ->
//   per layer: [wmma fp16 GEMM, W pre-converted+staged once -> g fp16] ->
//              [AGG pull: half-warp/edge uint2, 8 edges in flight, fp32 accum]
// h fp16. No fp32 atomics anywhere; CSR rebuilt every launch.

#define NMAX 100000
#define EMAX 1600000
#define SCAN_B 1024

__device__ __align__(16) __half g_buf[(size_t)NMAX * 64];   // fp16 gather buffer
__device__ __align__(16) __half h_buf[(size_t)NMAX * 64];   // fp16 activations
__device__ __align__(16) __half w1h_buf[128 * 64];          // W1 fp16
__device__ __align__(16) __half w2h_buf[64 * 64];           // W2 fp16
__device__ __align__(16) __half wch_buf[64 * 64];           // [Wmu | Wlv] fp16
__device__ float dis_buf[NMAX];
__device__ int   deg_buf[NMAX];
__device__ int   offs_buf[NMAX + 1];
__device__ int   cursor_buf[NMAX];
__device__ int   csr_buf[EMAX];
__device__ int   block_sums[128];

#define W_TASKS (128 * 64 + 64 * 64 + 64 * 64)   // 16384

// ---------------------------------------------------------------------------
// zero deg + one-time fp32->fp16 weight conversion (extra tail blocks).
__global__ void prep_kernel(const float* __restrict__ W1,
                            const float* __restrict__ W2,
                            const float* __restrict__ Wmu,
                            const float* __restrict__ Wlv, int N) {
    int i = blockIdx.x * blockDim.x + threadIdx.x;
    if (i < N) deg_buf[i] = 0;
    int j = i - N;
    if (j >= 0 && j < W_TASKS) {
        if (j < 128 * 64) {
            w1h_buf[j] = __float2half_rn(W1[j]);
        } else if (j < 128 * 64 + 64 * 64) {
            int t = j - 128 * 64;
            w2h_buf[t] = __float2half_rn(W2[t]);
        } else {
            int t = j - (128 * 64 + 64 * 64);
            int k = t >> 6, c = t & 63;
            wch_buf[t] = __float2half_rn(c < 32 ? Wmu[k * 32 + c] : Wlv[k * 32 + c - 32]);
        }
    }
}

__global__ void count_deg_kernel(const int* __restrict__ ei, int E) {
    int e = blockIdx.x * blockDim.x + threadIdx.x;
    if (e < E) atomicAdd(&deg_buf[ei[E + e]], 1);
}

// Phase 1 of scan + fused dis = rsqrt(deg+1).
__global__ void reduce_deg_kernel(int N) {
    int idx = blockIdx.x * SCAN_B + threadIdx.x;
    int v = (idx < N) ? deg_buf[idx] : 0;
    if (idx < N) dis_buf[idx] = rsqrtf((float)v + 1.0f);
    int s = v;
    #pragma unroll
    for (int o = 16; o; o >>= 1) s += __shfl_down_sync(0xffffffffu, s, o);
    __shared__ int ws[32];
    int lane = threadIdx.x & 31, w = threadIdx.x >> 5;
    if (lane == 0) ws[w] = s;
    __syncthreads();
    if (w == 0) {
        int t = ws[lane];
        #pragma unroll
        for (int o = 16; o; o >>= 1) t += __shfl_down_sync(0xffffffffu, t, o);
        if (lane == 0) block_sums[blockIdx.x] = t;
    }
}

__global__ void scan_sums_kernel(int nb, int N) {
    int tid = threadIdx.x;
    __shared__ int sh[128];
    int v = (tid < nb) ? block_sums[tid] : 0;
    sh[tid] = v;
    __syncthreads();
    #pragma unroll
    for (int o = 1; o < 128; o <<= 1) {
        int t = (tid >= o) ? sh[tid - o] : 0;
        __syncthreads();
        sh[tid] += t;
        __syncthreads();
    }
    if (tid < nb) block_sums[tid] = sh[tid] - v;   // exclusive
    if (tid == 0) offs_buf[N] = sh[127];
}

__global__ void scan_deg_kernel(int N) {
    int idx = blockIdx.x * SCAN_B + threadIdx.x;
    int v = (idx < N) ? deg_buf[idx] : 0;
    int lane = threadIdx.x & 31, w = threadIdx.x >> 5;
    int s = v;
    #pragma unroll
    for (int o = 1; o < 32; o <<= 1) {
        int t = __shfl_up_sync(0xffffffffu, s, o);
        if (lane >= o) s += t;
    }
    __shared__ int ws[32];
    if (lane == 31) ws[w] = s;
    __syncthreads();
    if (w == 0) {
        int t = ws[lane];
        #pragma unroll
        for (int o = 1; o < 32; o <<= 1) {
            int u = __shfl_up_sync(0xffffffffu, t, o);
            if (lane >= o) t += u;
        }
        ws[lane] = t;
    }
    __syncthreads();
    int excl = s - v + (w > 0 ? ws[w - 1] : 0) + block_sums[blockIdx.x];
    if (idx < N) {
        offs_buf[idx]   = excl;
        cursor_buf[idx] = excl;
    }
}

__global__ void fill_csr_kernel(const int* __restrict__ ei, int E) {
    int e = blockIdx.x * blockDim.x + threadIdx.x;
    if (e < E) {
        int dst = ei[E + e];
        int p = atomicAdd(&cursor_buf[dst], 1);
        csr_buf[p] = ei[e];  // src
    }
}

// ---------------------------------------------------------------------------
// WMMA GEMM + row-scale, fp16 in/out, fp32 accum:
//   out[i, 0:64] = half((X[i,:] @ W) * dis[i])
// 128 rows x 64 cols per block, 256 threads (8 warps), warp = 16 rows x 64 cols.
// W pre-converted fp16 in gmem, staged ONCE per block (pure uint4 copies).
// X staged per 32-k-tile (fp32->fp16 convert for layer 1, copy for fp16 layers).
#define XH_S 40   // Xh row stride (halves); 80B, 16B-multiple
#define WH_S 72   // Wh row stride (halves); 144B, 16B-multiple
#define ST_S 68   // Stg row stride (floats); 272B, 16B-multiple

template <int K, bool IN_HALF>
__global__ void __launch_bounds__(256, 3)
gemm_wmma_kernel(const void* __restrict__ Xv,
                 const __half* __restrict__ Wg,
                 __half* __restrict__ out, int N)
{
    constexpr int KT = 32;
    constexpr int STAGES = K / KT;
    // Xh:128*XH_S*2=10240B, Wh:K*WH_S*2 (<=18432B); Stg aliases all (34816B)
    __shared__ __align__(16) char sraw[128 * ST_S * 4];
    __half* Xh = (__half*)sraw;
    __half* Wh = (__half*)(sraw + 128 * XH_S * 2);
    float*  Stg = (float*)sraw;

    int tid  = threadIdx.x;
    int warp = tid >> 5;
    int row0 = blockIdx.x * 128;

    wmma::fragment<wmma::accumulator, 16, 16, 16, float> acc[4];
    #pragma unroll
    for (int c = 0; c < 4; c++) wmma::fill_fragment(acc[c], 0.0f);

    // ---- stage ALL of W once: K rows x 8 uint4-chunks (8 halves each) ----
    for (int i = tid; i < K * 8; i += 256) {
        int k = i >> 3, c8 = i & 7;
        *(uint4*)&Wh[k * WH_S + c8 * 8] = *(const uint4*)(Wg + k * 64 + c8 * 8);
    }

    for (int kt = 0; kt < STAGES; kt++) {
        // stage X slice [row0..+128][kt*KT..+KT]
        if (IN_HALF) {
            const __half* Xp = (const __half*)Xv;
            // 128 rows x 4 uint4-chunks (8 halves) = 512 tasks
            for (int i = tid; i < 512; i += 256) {
                int r = i >> 2, c8 = i & 3;
                int gr = row0 + r; if (gr >= N) gr = N - 1;
                uint4 v = *(const uint4*)(Xp + (size_t)gr * K + kt * KT + c8 * 8);
                *(uint4*)&Xh[r * XH_S + c8 * 8] = v;
            }
        } else {
            const float* Xp = (const float*)Xv;
            // 128 rows x 8 float4-chunks = 1024 tasks
            for (int i = tid; i < 1024; i += 256) {
                int r = i >> 3, c4 = i & 7;
                int gr = row0 + r; if (gr >= N) gr = N - 1;
                float4 v = *(const float4*)(Xp + (size_t)gr * K + kt * KT + c4 * 4);
                __half2 h0 = __float22half2_rn(make_float2(v.x, v.y));
                __half2 h1 = __float22half2_rn(make_float2(v.z, v.w));
                uint2 pk;
                pk.x = *(unsigned*)&h0;
                pk.y = *(unsigned*)&h1;
                *(uint2*)&Xh[r * XH_S + c4 * 4] = pk;
            }
        }
        __syncthreads();   // X slice (and, first iter, W) visible

        #pragma unroll
        for (int ks = 0; ks < KT / 16; ks++) {
            wmma::fragment<wmma::matrix_a, 16, 16, 16, __half, wmma::row_major> af;
            wmma::load_matrix_sync(af, &Xh[(warp * 16) * XH_S + ks * 16], XH_S);
            #pragma unroll
            for (int c = 0; c < 4; c++) {
                wmma::fragment<wmma::matrix_b, 16, 16, 16, __half, wmma::row_major> bf;
                wmma::load_matrix_sync(bf, &Wh[(kt * KT + ks * 16) * WH_S + c * 16], WH_S);
                wmma::mma_sync(acc[c], af, bf, acc[c]);
            }
        }
        __syncthreads();   // all warps done reading Xh before restage / Stg alias
    }

    // dump accumulators to fp32 staging (aliases Xh/Wh; synced above)
    #pragma unroll
    for (int c = 0; c < 4; c++)
        wmma::store_matrix_sync(&Stg[(warp * 16) * ST_S + c * 16], acc[c], ST_S,
                                wmma::mem_row_major);
    __syncthreads();

    // epilogue: scale by dis, convert to fp16, STG.128
    {
        int r = tid >> 1, hsel = tid & 1;
        int gr = row0 + r;
        if (gr < N) {
            float d = dis_buf[gr];
            const float* src = &Stg[r * ST_S + hsel * 32];
            __half* dst = out + (size_t)gr * 64 + hsel * 32;
            #pragma unroll
            for (int c8 = 0; c8 < 4; c8++) {
                float4 u = *(const float4*)(src + c8 * 8);
                float4 v = *(const float4*)(src + c8 * 8 + 4);
                __half2 p0 = __float22half2_rn(make_float2(u.x * d, u.y * d));
                __half2 p1 = __float22half2_rn(make_float2(u.z * d, u.w * d));
                __half2 p2 = __float22half2_rn(make_float2(v.x * d, v.y * d));
                __half2 p3 = __float22half2_rn(make_float2(v.z * d, v.w * d));
                uint4 pk;
                pk.x = *(unsigned*)&p0;
                pk.y = *(unsigned*)&p1;
                pk.z = *(unsigned*)&p2;
                pk.w = *(unsigned*)&p3;
                *(uint4*)(dst + c8 * 8) = pk;
            }
        }
    }
}

// ---------------------------------------------------------------------------
// Pull aggregation: one warp per dst node. Half-warp (16 lanes x uint2 = 128B
// = one cache line) covers one edge's fp16 row; 8 edges in flight per warp.
__device__ __forceinline__ float4 h4_to_f4(uint2 v) {
    __half2 a = *(__half2*)&v.x;
    __half2 b = *(__half2*)&v.y;
    float2 fa = __half22float2(a);
    float2 fb = __half22float2(b);
    return make_float4(fa.x, fa.y, fb.x, fb.y);
}

// OUTHALF: write fp16 h (intermediate layers). SPLIT: final fp32 mu/logvar.
template <bool RELU, bool SPLIT, bool OUTHALF>
__global__ void agg_kernel(const __half* __restrict__ g,
                           const float* __restrict__ ba,
                           const float* __restrict__ bb,
                           void* __restrict__ outv, int N)
{
    int warp = (int)((blockIdx.x * (unsigned)blockDim.x + threadIdx.x) >> 5);
    int lane = threadIdx.x & 31;
    if (warp >= N) return;
    int row  = warp;
    int half = lane >> 4;
    int li   = lane & 15;

    const uint2* gp = (const uint2*)g;   // 16 uint2 (64 halves) per row

    float4 a0 = make_float4(0.f, 0.f, 0.f, 0.f);
    float4 a1 = a0, a2 = a0, a3 = a0;
    if (half == 0) {
        float4 v = h4_to_f4(gp[(size_t)row * 16 + li]);   // self-loop term
        a0.x += v.x; a0.y += v.y; a0.z += v.z; a0.w += v.w;
    }

    int beg = offs_buf[row];
    int end = offs_buf[row + 1];
    int e = beg;
    for (; e + 7 < end; e += 8) {
        int s0 = csr_buf[e     + half];
        int s1 = csr_buf[e + 2 + half];
        int s2 = csr_buf[e + 4 + half];
        int s3 = csr_buf[e + 6 + half];
        float4 v0 = h4_to_f4(gp[(size_t)s0 * 16 + li]);
        float4 v1 = h4_to_f4(gp[(size_t)s1 * 16 + li]);
        float4 v2 = h4_to_f4(gp[(size_t)s2 * 16 + li]);
        float4 v3 = h4_to_f4(gp[(size_t)s3 * 16 + li]);
        a0.x += v0.x; a0.y += v0.y; a0.z += v0.z; a0.w += v0.w;
        a1.x += v1.x; a1.y += v1.y; a1.z += v1.z; a1.w += v1.w;
        a2.x += v2.x; a2.y += v2.y; a2.z += v2.z; a2.w += v2.w;
        a3.x += v3.x; a3.y += v3.y; a3.z += v3.z; a3.w += v3.w;
    }
    for (; e + 1 < end; e += 2) {
        int s = csr_buf[e + half];
        float4 v = h4_to_f4(gp[(size_t)s * 16 + li]);
        a0.x += v.x; a0.y += v.y; a0.z += v.z; a0.w += v.w;
    }
    if (e < end && half == 0) {
        float4 v = h4_to_f4(gp[(size_t)csr_buf[e] * 16 + li]);
        a0.x += v.x; a0.y += v.y; a0.z += v.z; a0.w += v.w;
    }
    a0.x += a1.x + a2.x + a3.x;
    a0.y += a1.y + a2.y + a3.y;
    a0.z += a1.z + a2.z + a3.z;
    a0.w += a1.w + a2.w + a3.w;

    a0.x += __shfl_xor_sync(0xffffffffu, a0.x, 16);
    a0.y += __shfl_xor_sync(0xffffffffu, a0.y, 16);
    a0.z += __shfl_xor_sync(0xffffffffu, a0.z, 16);
    a0.w += __shfl_xor_sync(0xffffffffu, a0.w, 16);

    if (half == 0) {
        float d = dis_buf[row];
        int c0 = 4 * li;
        float4 b4;
        if (SPLIT) {
            b4.x = (c0     < 32) ? ba[c0]     : bb[c0 - 32];
            b4.y = (c0 + 1 < 32) ? ba[c0 + 1] : bb[c0 + 1 - 32];
            b4.z = (c0 + 2 < 32) ? ba[c0 + 2] : bb[c0 + 2 - 32];
            b4.w = (c0 + 3 < 32) ? ba[c0 + 3] : bb[c0 + 3 - 32];
        } else {
            b4 = *(const float4*)(ba + c0);
        }
        float4 r;
        r.x = fmaf(d, a0.x, b4.x);
        r.y = fmaf(d, a0.y, b4.y);
        r.z = fmaf(d, a0.z, b4.z);
        r.w = fmaf(d, a0.w, b4.w);
        if (RELU) {
            r.x = fmaxf(r.x, 0.f); r.y = fmaxf(r.y, 0.f);
            r.z = fmaxf(r.z, 0.f); r.w = fmaxf(r.w, 0.f);
        }
        if (OUTHALF) {
            __half2 q0 = __float22half2_rn(make_float2(r.x, r.y));
            __half2 q1 = __float22half2_rn(make_float2(r.z, r.w));
            uint2 pk;
            pk.x = *(unsigned*)&q0;
            pk.y = *(unsigned*)&q1;
            ((uint2*)outv)[(size_t)row * 16 + li] = pk;
        } else if (SPLIT) {
            float* out = (float*)outv;
            if (li < 8) ((float4*)out)[(size_t)row * 8 + li] = r;                          // mu
            else        ((float4*)(out + (size_t)N * 32))[(size_t)row * 8 + (li - 8)] = r; // logvar
        } else {
            ((float4*)outv)[(size_t)row * 16 + li] = r;
        }
    }
}

// ---------------------------------------------------------------------------
extern "C" void kernel_launch(void* const* d_in, const int* in_sizes, int n_in,
                              void* d_out, int out_size)
{
    const float* x   = (const float*)d_in[0];
    const int*   ei  = (const int*)  d_in[1];
    const float* W1  = (const float*)d_in[2];
    const float* b1  = (const float*)d_in[3];
    const float* W2  = (const float*)d_in[4];
    const float* b2  = (const float*)d_in[5];
    const float* Wmu = (const float*)d_in[6];
    const float* bmu = (const float*)d_in[7];
    const float* Wlv = (const float*)d_in[8];
    const float* blv = (const float*)d_in[9];
    float* out = (float*)d_out;

    int N = in_sizes[0] / 128;
    int E = in_sizes[1] / 2;
    int nb = (N + SCAN_B - 1) / SCAN_B;

    __half* g = nullptr;
    __half* h = nullptr;
    __half* w1h = nullptr;
    __half* w2h = nullptr;
    __half* wch = nullptr;
    cudaGetSymbolAddress((void**)&g, g_buf);
    cudaGetSymbolAddress((void**)&h, h_buf);
    cudaGetSymbolAddress((void**)&w1h, w1h_buf);
    cudaGetSymbolAddress((void**)&w2h, w2h_buf);
    cudaGetSymbolAddress((void**)&wch, wch_buf);

    int gemm_grid = (N + 127) / 128;
    int agg_grid  = (N + 7) / 8;

    prep_kernel<<<(N + W_TASKS + 255) / 256, 256>>>(W1, W2, Wmu, Wlv, N);        // idx 0
    count_deg_kernel<<<(E + 255) / 256, 256>>>(ei, E);                           // idx 1
    reduce_deg_kernel<<<nb, SCAN_B>>>(N);                                        // idx 2 (also dis)
    gemm_wmma_kernel<128, false><<<gemm_grid, 256>>>(x, w1h, g, N);              // idx 3 (profiled)
    scan_sums_kernel<<<1, 128>>>(nb, N);
    scan_deg_kernel<<<nb, SCAN_B>>>(N);
    fill_csr_kernel<<<(E + 255) / 256, 256>>>(ei, E);

    agg_kernel<true, false, true><<<agg_grid, 256>>>(g, b1, nullptr, h, N);

    gemm_wmma_kernel<64, true><<<gemm_grid, 256>>>(h, w2h, g, N);
    agg_kernel<true, false, true><<<agg_grid, 256>>>(g, b2, nullptr, h, N);

    gemm_wmma_kernel<64, true><<<gemm_grid, 256>>>(h, wch, g, N);
    agg_kernel<false, true, false><<<agg_grid, 256>>>(g, bmu, blv, out, N);
}

// round 16
// speedup vs baseline: 1.1798x; 1.0460x over previous
#include <cuda_runtime.h>
#include <cuda_fp16.h>
#include <cuda_bf16.h>
#include <mma.h>

using namespace nvcuda;

// GCN encoder: 2x GCNConv(relu) + fused mu/logvar GCNConv heads.
//   [prep: zero deg + convert all W to fp16] -> count -> [reduce+dis] ->
//   [wmma gemm1, idx 3] -> scan -> CSR fill ->
//   per layer: [wmma fp16 GEMM, 64-row blocks, warp=16x32 (high occ) -> g fp16] ->
//              [AGG pull: half-warp/edge uint2, 8 edges in flight, fp32 accum]
// h fp16. No fp32 atomics anywhere; CSR rebuilt every launch.

#define NMAX 100000
#define EMAX 1600000
#define SCAN_B 1024

__device__ __align__(16) __half g_buf[(size_t)NMAX * 64];   // fp16 gather buffer
__device__ __align__(16) __half h_buf[(size_t)NMAX * 64];   // fp16 activations
__device__ __align__(16) __half w1h_buf[128 * 64];          // W1 fp16
__device__ __align__(16) __half w2h_buf[64 * 64];           // W2 fp16
__device__ __align__(16) __half wch_buf[64 * 64];           // [Wmu | Wlv] fp16
__device__ float dis_buf[NMAX];
__device__ int   deg_buf[NMAX];
__device__ int   offs_buf[NMAX + 1];
__device__ int   cursor_buf[NMAX];
__device__ int   csr_buf[EMAX];
__device__ int   block_sums[128];

#define W_TASKS (128 * 64 + 64 * 64 + 64 * 64)   // 16384

// ---------------------------------------------------------------------------
// zero deg + one-time fp32->fp16 weight conversion (extra tail blocks).
__global__ void prep_kernel(const float* __restrict__ W1,
                            const float* __restrict__ W2,
                            const float* __restrict__ Wmu,
                            const float* __restrict__ Wlv, int N) {
    int i = blockIdx.x * blockDim.x + threadIdx.x;
    if (i < N) deg_buf[i] = 0;
    int j = i - N;
    if (j >= 0 && j < W_TASKS) {
        if (j < 128 * 64) {
            w1h_buf[j] = __float2half_rn(W1[j]);
        } else if (j < 128 * 64 + 64 * 64) {
            int t = j - 128 * 64;
            w2h_buf[t] = __float2half_rn(W2[t]);
        } else {
            int t = j - (128 * 64 + 64 * 64);
            int k = t >> 6, c = t & 63;
            wch_buf[t] = __float2half_rn(c < 32 ? Wmu[k * 32 + c] : Wlv[k * 32 + c - 32]);
        }
    }
}

__global__ void count_deg_kernel(const int* __restrict__ ei, int E) {
    int e = blockIdx.x * blockDim.x + threadIdx.x;
    if (e < E) atomicAdd(&deg_buf[ei[E + e]], 1);
}

// Phase 1 of scan + fused dis = rsqrt(deg+1).
__global__ void reduce_deg_kernel(int N) {
    int idx = blockIdx.x * SCAN_B + threadIdx.x;
    int v = (idx < N) ? deg_buf[idx] : 0;
    if (idx < N) dis_buf[idx] = rsqrtf((float)v + 1.0f);
    int s = v;
    #pragma unroll
    for (int o = 16; o; o >>= 1) s += __shfl_down_sync(0xffffffffu, s, o);
    __shared__ int ws[32];
    int lane = threadIdx.x & 31, w = threadIdx.x >> 5;
    if (lane == 0) ws[w] = s;
    __syncthreads();
    if (w == 0) {
        int t = ws[lane];
        #pragma unroll
        for (int o = 16; o; o >>= 1) t += __shfl_down_sync(0xffffffffu, t, o);
        if (lane == 0) block_sums[blockIdx.x] = t;
    }
}

__global__ void scan_sums_kernel(int nb, int N) {
    int tid = threadIdx.x;
    __shared__ int sh[128];
    int v = (tid < nb) ? block_sums[tid] : 0;
    sh[tid] = v;
    __syncthreads();
    #pragma unroll
    for (int o = 1; o < 128; o <<= 1) {
        int t = (tid >= o) ? sh[tid - o] : 0;
        __syncthreads();
        sh[tid] += t;
        __syncthreads();
    }
    if (tid < nb) block_sums[tid] = sh[tid] - v;   // exclusive
    if (tid == 0) offs_buf[N] = sh[127];
}

__global__ void scan_deg_kernel(int N) {
    int idx = blockIdx.x * SCAN_B + threadIdx.x;
    int v = (idx < N) ? deg_buf[idx] : 0;
    int lane = threadIdx.x & 31, w = threadIdx.x >> 5;
    int s = v;
    #pragma unroll
    for (int o = 1; o < 32; o <<= 1) {
        int t = __shfl_up_sync(0xffffffffu, s, o);
        if (lane >= o) s += t;
    }
    __shared__ int ws[32];
    if (lane == 31) ws[w] = s;
    __syncthreads();
    if (w == 0) {
        int t = ws[lane];
        #pragma unroll
        for (int o = 1; o < 32; o <<= 1) {
            int u = __shfl_up_sync(0xffffffffu, t, o);
            if (lane >= o) t += u;
        }
        ws[lane] = t;
    }
    __syncthreads();
    int excl = s - v + (w > 0 ? ws[w - 1] : 0) + block_sums[blockIdx.x];
    if (idx < N) {
        offs_buf[idx]   = excl;
        cursor_buf[idx] = excl;
    }
}

__global__ void fill_csr_kernel(const int* __restrict__ ei, int E) {
    int e = blockIdx.x * blockDim.x + threadIdx.x;
    if (e < E) {
        int dst = ei[E + e];
        int p = atomicAdd(&cursor_buf[dst], 1);
        csr_buf[p] = ei[e];  // src
    }
}

// ---------------------------------------------------------------------------
// WMMA GEMM + row-scale, fp16 in/out, fp32 accum:
//   out[i, 0:64] = half((X[i,:] @ W) * dis[i])
// Block = 64 rows x 64 cols, 256 threads (8 warps), warp = 16 rows x 32 cols
// (rg = warp>>1, cg = warp&1). 2 acc fragments/warp -> low regs, 5 blocks/SM.
// One-shot staging; barrier-free K loop. W pre-converted fp16 in gmem.
#define WH_S 72   // Wh row stride (halves); 144B, 16B-multiple
#define ST_S 68   // Stg row stride (floats); 272B, 16B-multiple

template <int K, bool IN_HALF>
__global__ void __launch_bounds__(256)
gemm_wmma_kernel(const void* __restrict__ Xv,
                 const __half* __restrict__ Wg,
                 __half* __restrict__ out, int N)
{
    constexpr int XS = K + 8;                               // Xh row stride (halves)
    constexpr int XB = 64 * XS * 2;                         // Xh bytes
    constexpr int AB = XB + K * WH_S * 2;                   // Xh + Wh bytes
    constexpr int SB = (AB > 64 * ST_S * 4) ? AB : 64 * ST_S * 4;
    __shared__ __align__(16) char sraw[SB];
    __half* Xh = (__half*)sraw;
    __half* Wh = (__half*)(sraw + XB);
    float*  Stg = (float*)sraw;                             // aliases Xh (post-MMA)

    int tid  = threadIdx.x;
    int warp = tid >> 5;
    int rg = warp >> 1;      // row group 0..3 (16 rows each)
    int cg = warp & 1;       // col group 0..1 (32 cols each)
    int row0 = blockIdx.x * 64;

    // ---- stage W once: K rows x 8 uint4-chunks ----
    for (int i = tid; i < K * 8; i += 256) {
        int k = i >> 3, c8 = i & 7;
        *(uint4*)&Wh[k * WH_S + c8 * 8] = *(const uint4*)(Wg + k * 64 + c8 * 8);
    }
    // ---- stage X once (64 rows x K) ----
    if (IN_HALF) {
        const __half* Xp = (const __half*)Xv;
        constexpr int CH = K / 8;                // uint4 chunks per row
        for (int i = tid; i < 64 * CH; i += 256) {
            int r = i / CH, c8 = i % CH;
            int gr = row0 + r; if (gr >= N) gr = N - 1;
            uint4 v = *(const uint4*)(Xp + (size_t)gr * K + c8 * 8);
            *(uint4*)&Xh[r * XS + c8 * 8] = v;
        }
    } else {
        const float* Xp = (const float*)Xv;
        constexpr int CH = K / 4;                // float4 chunks per row
        for (int i = tid; i < 64 * CH; i += 256) {
            int r = i / CH, c4 = i % CH;
            int gr = row0 + r; if (gr >= N) gr = N - 1;
            float4 v = *(const float4*)(Xp + (size_t)gr * K + c4 * 4);
            __half2 h0 = __float22half2_rn(make_float2(v.x, v.y));
            __half2 h1 = __float22half2_rn(make_float2(v.z, v.w));
            uint2 pk;
            pk.x = *(unsigned*)&h0;
            pk.y = *(unsigned*)&h1;
            *(uint2*)&Xh[r * XS + c4 * 4] = pk;
        }
    }
    __syncthreads();

    // ---- barrier-free K loop: K/16 ksteps x 2 col-tiles ----
    wmma::fragment<wmma::accumulator, 16, 16, 16, float> acc[2];
    #pragma unroll
    for (int c = 0; c < 2; c++) wmma::fill_fragment(acc[c], 0.0f);

    #pragma unroll
    for (int ks = 0; ks < K / 16; ks++) {
        wmma::fragment<wmma::matrix_a, 16, 16, 16, __half, wmma::row_major> af;
        wmma::load_matrix_sync(af, &Xh[(rg * 16) * XS + ks * 16], XS);
        #pragma unroll
        for (int c = 0; c < 2; c++) {
            wmma::fragment<wmma::matrix_b, 16, 16, 16, __half, wmma::row_major> bf;
            wmma::load_matrix_sync(bf, &Wh[(ks * 16) * WH_S + cg * 32 + c * 16], WH_S);
            wmma::mma_sync(acc[c], af, bf, acc[c]);
        }
    }
    __syncthreads();   // all warps done reading Xh/Wh before Stg alias overwrite

    #pragma unroll
    for (int c = 0; c < 2; c++)
        wmma::store_matrix_sync(&Stg[(rg * 16) * ST_S + cg * 32 + c * 16], acc[c],
                                ST_S, wmma::mem_row_major);
    __syncthreads();

    // epilogue: scale by dis, convert to fp16, STG.128 (64 rows x 2 half-rows)
    if (tid < 128) {
        int r = tid >> 1, hsel = tid & 1;
        int gr = row0 + r;
        if (gr < N) {
            float d = dis_buf[gr];
            const float* src = &Stg[r * ST_S + hsel * 32];
            __half* dst = out + (size_t)gr * 64 + hsel * 32;
            #pragma unroll
            for (int c8 = 0; c8 < 4; c8++) {
                float4 u = *(const float4*)(src + c8 * 8);
                float4 v = *(const float4*)(src + c8 * 8 + 4);
                __half2 p0 = __float22half2_rn(make_float2(u.x * d, u.y * d));
                __half2 p1 = __float22half2_rn(make_float2(u.z * d, u.w * d));
                __half2 p2 = __float22half2_rn(make_float2(v.x * d, v.y * d));
                __half2 p3 = __float22half2_rn(make_float2(v.z * d, v.w * d));
                uint4 pk;
                pk.x = *(unsigned*)&p0;
                pk.y = *(unsigned*)&p1;
                pk.z = *(unsigned*)&p2;
                pk.w = *(unsigned*)&p3;
                *(uint4*)(dst + c8 * 8) = pk;
            }
        }
    }
}

// ---------------------------------------------------------------------------
// Pull aggregation: one warp per dst node. Half-warp (16 lanes x uint2 = 128B
// = one cache line) covers one edge's fp16 row; 8 edges in flight per warp.
__device__ __forceinline__ float4 h4_to_f4(uint2 v) {
    __half2 a = *(__half2*)&v.x;
    __half2 b = *(__half2*)&v.y;
    float2 fa = __half22float2(a);
    float2 fb = __half22float2(b);
    return make_float4(fa.x, fa.y, fb.x, fb.y);
}

// OUTHALF: write fp16 h (intermediate layers). SPLIT: final fp32 mu/logvar.
template <bool RELU, bool SPLIT, bool OUTHALF>
__global__ void agg_kernel(const __half* __restrict__ g,
                           const float* __restrict__ ba,
                           const float* __restrict__ bb,
                           void* __restrict__ outv, int N)
{
    int warp = (int)((blockIdx.x * (unsigned)blockDim.x + threadIdx.x) >> 5);
    int lane = threadIdx.x & 31;
    if (warp >= N) return;
    int row  = warp;
    int half = lane >> 4;
    int li   = lane & 15;

    const uint2* gp = (const uint2*)g;   // 16 uint2 (64 halves) per row

    float4 a0 = make_float4(0.f, 0.f, 0.f, 0.f);
    float4 a1 = a0, a2 = a0, a3 = a0;
    if (half == 0) {
        float4 v = h4_to_f4(gp[(size_t)row * 16 + li]);   // self-loop term
        a0.x += v.x; a0.y += v.y; a0.z += v.z; a0.w += v.w;
    }

    int beg = offs_buf[row];
    int end = offs_buf[row + 1];
    int e = beg;
    for (; e + 7 < end; e += 8) {
        int s0 = csr_buf[e     + half];
        int s1 = csr_buf[e + 2 + half];
        int s2 = csr_buf[e + 4 + half];
        int s3 = csr_buf[e + 6 + half];
        float4 v0 = h4_to_f4(gp[(size_t)s0 * 16 + li]);
        float4 v1 = h4_to_f4(gp[(size_t)s1 * 16 + li]);
        float4 v2 = h4_to_f4(gp[(size_t)s2 * 16 + li]);
        float4 v3 = h4_to_f4(gp[(size_t)s3 * 16 + li]);
        a0.x += v0.x; a0.y += v0.y; a0.z += v0.z; a0.w += v0.w;
        a1.x += v1.x; a1.y += v1.y; a1.z += v1.z; a1.w += v1.w;
        a2.x += v2.x; a2.y += v2.y; a2.z += v2.z; a2.w += v2.w;
        a3.x += v3.x; a3.y += v3.y; a3.z += v3.z; a3.w += v3.w;
    }
    for (; e + 1 < end; e += 2) {
        int s = csr_buf[e + half];
        float4 v = h4_to_f4(gp[(size_t)s * 16 + li]);
        a0.x += v.x; a0.y += v.y; a0.z += v.z; a0.w += v.w;
    }
    if (e < end && half == 0) {
        float4 v = h4_to_f4(gp[(size_t)csr_buf[e] * 16 + li]);
        a0.x += v.x; a0.y += v.y; a0.z += v.z; a0.w += v.w;
    }
    a0.x += a1.x + a2.x + a3.x;
    a0.y += a1.y + a2.y + a3.y;
    a0.z += a1.z + a2.z + a3.z;
    a0.w += a1.w + a2.w + a3.w;

    a0.x += __shfl_xor_sync(0xffffffffu, a0.x, 16);
    a0.y += __shfl_xor_sync(0xffffffffu, a0.y, 16);
    a0.z += __shfl_xor_sync(0xffffffffu, a0.z, 16);
    a0.w += __shfl_xor_sync(0xffffffffu, a0.w, 16);

    if (half == 0) {
        float d = dis_buf[row];
        int c0 = 4 * li;
        float4 b4;
        if (SPLIT) {
            b4.x = (c0     < 32) ? ba[c0]     : bb[c0 - 32];
            b4.y = (c0 + 1 < 32) ? ba[c0 + 1] : bb[c0 + 1 - 32];
            b4.z = (c0 + 2 < 32) ? ba[c0 + 2] : bb[c0 + 2 - 32];
            b4.w = (c0 + 3 < 32) ? ba[c0 + 3] : bb[c0 + 3 - 32];
        } else {
            b4 = *(const float4*)(ba + c0);
        }
        float4 r;
        r.x = fmaf(d, a0.x, b4.x);
        r.y = fmaf(d, a0.y, b4.y);
        r.z = fmaf(d, a0.z, b4.z);
        r.w = fmaf(d, a0.w, b4.w);
        if (RELU) {
            r.x = fmaxf(r.x, 0.f); r.y = fmaxf(r.y, 0.f);
            r.z = fmaxf(r.z, 0.f); r.w = fmaxf(r.w, 0.f);
        }
        if (OUTHALF) {
            __half2 q0 = __float22half2_rn(make_float2(r.x, r.y));
            __half2 q1 = __float22half2_rn(make_float2(r.z, r.w));
            uint2 pk;
            pk.x = *(unsigned*)&q0;
            pk.y = *(unsigned*)&q1;
            ((uint2*)outv)[(size_t)row * 16 + li] = pk;
        } else if (SPLIT) {
            float* out = (float*)outv;
            if (li < 8) ((float4*)out)[(size_t)row * 8 + li] = r;                          // mu
            else        ((float4*)(out + (size_t)N * 32))[(size_t)row * 8 + (li - 8)] = r; // logvar
        } else {
            ((float4*)outv)[(size_t)row * 16 + li] = r;
        }
    }
}

// ---------------------------------------------------------------------------
extern "C" void kernel_launch(void* const* d_in, const int* in_sizes, int n_in,
                              void* d_out, int out_size)
{
    const float* x   = (const float*)d_in[0];
    const int*   ei  = (const int*)  d_in[1];
    const float* W1  = (const float*)d_in[2];
    const float* b1  = (const float*)d_in[3];
    const float* W2  = (const float*)d_in[4];
    const float* b2  = (const float*)d_in[5];
    const float* Wmu = (const float*)d_in[6];
    const float* bmu = (const float*)d_in[7];
    const float* Wlv = (const float*)d_in[8];
    const float* blv = (const float*)d_in[9];
    float* out = (float*)d_out;

    int N = in_sizes[0] / 128;
    int E = in_sizes[1] / 2;
    int nb = (N + SCAN_B - 1) / SCAN_B;

    __half* g = nullptr;
    __half* h = nullptr;
    __half* w1h = nullptr;
    __half* w2h = nullptr;
    __half* wch = nullptr;
    cudaGetSymbolAddress((void**)&g, g_buf);
    cudaGetSymbolAddress((void**)&h, h_buf);
    cudaGetSymbolAddress((void**)&w1h, w1h_buf);
    cudaGetSymbolAddress((void**)&w2h, w2h_buf);
    cudaGetSymbolAddress((void**)&wch, wch_buf);

    int gemm_grid = (N + 63) / 64;
    int agg_grid  = (N + 7) / 8;

    prep_kernel<<<(N + W_TASKS + 255) / 256, 256>>>(W1, W2, Wmu, Wlv, N);        // idx 0
    count_deg_kernel<<<(E + 255) / 256, 256>>>(ei, E);                           // idx 1
    reduce_deg_kernel<<<nb, SCAN_B>>>(N);                                        // idx 2 (also dis)
    gemm_wmma_kernel<128, false><<<gemm_grid, 256>>>(x, w1h, g, N);              // idx 3 (profiled)
    scan_sums_kernel<<<1, 128>>>(nb, N);
    scan_deg_kernel<<<nb, SCAN_B>>>(N);
    fill_csr_kernel<<<(E + 255) / 256, 256>>>(ei, E);

    agg_kernel<true, false, true><<<agg_grid, 256>>>(g, b1, nullptr, h, N);

    gemm_wmma_kernel<64, true><<<gemm_grid, 256>>>(h, w2h, g, N);
    agg_kernel<true, false, true><<<agg_grid, 256>>>(g, b2, nullptr, h, N);

    gemm_wmma_kernel<64, true><<<gemm_grid, 256>>>(h, wch, g, N);
    agg_kernel<false, true, false><<<agg_grid, 256>>>(g, bmu, blv, out, N);
}

// round 17
// speedup vs baseline: 1.2142x; 1.0292x over previous
#include <cuda_runtime.h>
#include <cuda_fp16.h>
#include <cuda_bf16.h>
#include <mma.h>

using namespace nvcuda;

// GCN encoder: 2x GCNConv(relu) + fused mu/logvar GCNConv heads.
//   [prep: zero deg + convert all W to fp16] -> count -> [reduce+dis] ->
//   [wmma gemm1, idx 3] -> scan -> CSR fill ->
//   per layer: [wmma fp16 GEMM, batched-MLP staging -> g fp16] ->
//              [AGG pull: half-warp/edge uint2, 16 edges in flight, fp32 accum]
// h fp16. No fp32 atomics anywhere; CSR rebuilt every launch.

#define NMAX 100000
#define EMAX 1600000
#define SCAN_B 1024

__device__ __align__(16) __half g_buf[(size_t)NMAX * 64];   // fp16 gather buffer
__device__ __align__(16) __half h_buf[(size_t)NMAX * 64];   // fp16 activations
__device__ __align__(16) __half w1h_buf[128 * 64];          // W1 fp16
__device__ __align__(16) __half w2h_buf[64 * 64];           // W2 fp16
__device__ __align__(16) __half wch_buf[64 * 64];           // [Wmu | Wlv] fp16
__device__ float dis_buf[NMAX];
__device__ int   deg_buf[NMAX];
__device__ int   offs_buf[NMAX + 1];
__device__ int   cursor_buf[NMAX];
__device__ int   csr_buf[EMAX];
__device__ int   block_sums[128];

#define W_TASKS (128 * 64 + 64 * 64 + 64 * 64)   // 16384

// ---------------------------------------------------------------------------
// zero deg + one-time fp32->fp16 weight conversion (extra tail blocks).
__global__ void prep_kernel(const float* __restrict__ W1,
                            const float* __restrict__ W2,
                            const float* __restrict__ Wmu,
                            const float* __restrict__ Wlv, int N) {
    int i = blockIdx.x * blockDim.x + threadIdx.x;
    if (i < N) deg_buf[i] = 0;
    int j = i - N;
    if (j >= 0 && j < W_TASKS) {
        if (j < 128 * 64) {
            w1h_buf[j] = __float2half_rn(W1[j]);
        } else if (j < 128 * 64 + 64 * 64) {
            int t = j - 128 * 64;
            w2h_buf[t] = __float2half_rn(W2[t]);
        } else {
            int t = j - (128 * 64 + 64 * 64);
            int k = t >> 6, c = t & 63;
            wch_buf[t] = __float2half_rn(c < 32 ? Wmu[k * 32 + c] : Wlv[k * 32 + c - 32]);
        }
    }
}

__global__ void count_deg_kernel(const int* __restrict__ ei, int E) {
    int e = blockIdx.x * blockDim.x + threadIdx.x;
    if (e < E) atomicAdd(&deg_buf[ei[E + e]], 1);
}

// Phase 1 of scan + fused dis = rsqrt(deg+1).
__global__ void reduce_deg_kernel(int N) {
    int idx = blockIdx.x * SCAN_B + threadIdx.x;
    int v = (idx < N) ? deg_buf[idx] : 0;
    if (idx < N) dis_buf[idx] = rsqrtf((float)v + 1.0f);
    int s = v;
    #pragma unroll
    for (int o = 16; o; o >>= 1) s += __shfl_down_sync(0xffffffffu, s, o);
    __shared__ int ws[32];
    int lane = threadIdx.x & 31, w = threadIdx.x >> 5;
    if (lane == 0) ws[w] = s;
    __syncthreads();
    if (w == 0) {
        int t = ws[lane];
        #pragma unroll
        for (int o = 16; o; o >>= 1) t += __shfl_down_sync(0xffffffffu, t, o);
        if (lane == 0) block_sums[blockIdx.x] = t;
    }
}

__global__ void scan_sums_kernel(int nb, int N) {
    int tid = threadIdx.x;
    __shared__ int sh[128];
    int v = (tid < nb) ? block_sums[tid] : 0;
    sh[tid] = v;
    __syncthreads();
    #pragma unroll
    for (int o = 1; o < 128; o <<= 1) {
        int t = (tid >= o) ? sh[tid - o] : 0;
        __syncthreads();
        sh[tid] += t;
        __syncthreads();
    }
    if (tid < nb) block_sums[tid] = sh[tid] - v;   // exclusive
    if (tid == 0) offs_buf[N] = sh[127];
}

__global__ void scan_deg_kernel(int N) {
    int idx = blockIdx.x * SCAN_B + threadIdx.x;
    int v = (idx < N) ? deg_buf[idx] : 0;
    int lane = threadIdx.x & 31, w = threadIdx.x >> 5;
    int s = v;
    #pragma unroll
    for (int o = 1; o < 32; o <<= 1) {
        int t = __shfl_up_sync(0xffffffffu, s, o);
        if (lane >= o) s += t;
    }
    __shared__ int ws[32];
    if (lane == 31) ws[w] = s;
    __syncthreads();
    if (w == 0) {
        int t = ws[lane];
        #pragma unroll
        for (int o = 1; o < 32; o <<= 1) {
            int u = __shfl_up_sync(0xffffffffu, t, o);
            if (lane >= o) t += u;
        }
        ws[lane] = t;
    }
    __syncthreads();
    int excl = s - v + (w > 0 ? ws[w - 1] : 0) + block_sums[blockIdx.x];
    if (idx < N) {
        offs_buf[idx]   = excl;
        cursor_buf[idx] = excl;
    }
}

__global__ void fill_csr_kernel(const int* __restrict__ ei, int E) {
    int e = blockIdx.x * blockDim.x + threadIdx.x;
    if (e < E) {
        int dst = ei[E + e];
        int p = atomicAdd(&cursor_buf[dst], 1);
        csr_buf[p] = ei[e];  // src
    }
}

// ---------------------------------------------------------------------------
// WMMA GEMM + row-scale, fp16 in/out, fp32 accum:
//   out[i, 0:64] = half((X[i,:] @ W) * dis[i])
// Block = 64 rows x 64 cols, 256 threads (8 warps), warp = 16 rows x 32 cols.
// Staging batches ALL global loads into registers first (MLP ~12/thread),
// then converts/stores -- breaks the LDG->cvt in-order serialization.
#define WH_S 72   // Wh row stride (halves); 144B, 16B-multiple
#define ST_S 68   // Stg row stride (floats); 272B, 16B-multiple

template <int K, bool IN_HALF>
__global__ void __launch_bounds__(256)
gemm_wmma_kernel(const void* __restrict__ Xv,
                 const __half* __restrict__ Wg,
                 __half* __restrict__ out, int N)
{
    constexpr int XS = K + 8;                               // Xh row stride (halves)
    constexpr int XB = 64 * XS * 2;                         // Xh bytes
    constexpr int AB = XB + K * WH_S * 2;                   // Xh + Wh bytes
    constexpr int SB = (AB > 64 * ST_S * 4) ? AB : 64 * ST_S * 4;
    __shared__ __align__(16) char sraw[SB];
    __half* Xh = (__half*)sraw;
    __half* Wh = (__half*)(sraw + XB);
    float*  Stg = (float*)sraw;                             // aliases Xh (post-MMA)

    int tid  = threadIdx.x;
    int warp = tid >> 5;
    int rg = warp >> 1;      // row group 0..3 (16 rows each)
    int cg = warp & 1;       // col group 0..1 (32 cols each)
    int row0 = blockIdx.x * 64;

    // ---- batched staging: issue ALL loads, then all cvt/STS ----
    constexpr int WT = (K * 8) / 256;        // W uint4 tasks per thread (4 or 2)
    uint4 wv[WT];
    #pragma unroll
    for (int j = 0; j < WT; j++) {
        int i = j * 256 + tid;
        int k = i >> 3, c8 = i & 7;
        wv[j] = *(const uint4*)(Wg + k * 64 + c8 * 8);
    }
    if (IN_HALF) {
        const __half* Xp = (const __half*)Xv;
        constexpr int CH = K / 8;            // uint4 chunks per row
        constexpr int XT = (64 * CH) / 256;  // 2 for K=64
        uint4 xv[XT];
        #pragma unroll
        for (int j = 0; j < XT; j++) {
            int i = j * 256 + tid;
            int r = i / CH, c8 = i % CH;
            int gr = row0 + r; if (gr >= N) gr = N - 1;
            xv[j] = *(const uint4*)(Xp + (size_t)gr * K + c8 * 8);
        }
        #pragma unroll
        for (int j = 0; j < XT; j++) {
            int i = j * 256 + tid;
            int r = i / CH, c8 = i % CH;
            *(uint4*)&Xh[r * XS + c8 * 8] = xv[j];
        }
    } else {
        const float* Xp = (const float*)Xv;
        constexpr int CH = K / 4;            // float4 chunks per row
        constexpr int XT = (64 * CH) / 256;  // 8 for K=128
        float4 xv[XT];
        #pragma unroll
        for (int j = 0; j < XT; j++) {
            int i = j * 256 + tid;
            int r = i / CH, c4 = i % CH;
            int gr = row0 + r; if (gr >= N) gr = N - 1;
            xv[j] = *(const float4*)(Xp + (size_t)gr * K + c4 * 4);
        }
        #pragma unroll
        for (int j = 0; j < XT; j++) {
            int i = j * 256 + tid;
            int r = i / CH, c4 = i % CH;
            __half2 h0 = __float22half2_rn(make_float2(xv[j].x, xv[j].y));
            __half2 h1 = __float22half2_rn(make_float2(xv[j].z, xv[j].w));
            uint2 pk;
            pk.x = *(unsigned*)&h0;
            pk.y = *(unsigned*)&h1;
            *(uint2*)&Xh[r * XS + c4 * 4] = pk;
        }
    }
    #pragma unroll
    for (int j = 0; j < WT; j++) {
        int i = j * 256 + tid;
        int k = i >> 3, c8 = i & 7;
        *(uint4*)&Wh[k * WH_S + c8 * 8] = wv[j];
    }
    __syncthreads();

    // ---- barrier-free K loop: K/16 ksteps x 2 col-tiles ----
    wmma::fragment<wmma::accumulator, 16, 16, 16, float> acc[2];
    #pragma unroll
    for (int c = 0; c < 2; c++) wmma::fill_fragment(acc[c], 0.0f);

    #pragma unroll
    for (int ks = 0; ks < K / 16; ks++) {
        wmma::fragment<wmma::matrix_a, 16, 16, 16, __half, wmma::row_major> af;
        wmma::load_matrix_sync(af, &Xh[(rg * 16) * XS + ks * 16], XS);
        #pragma unroll
        for (int c = 0; c < 2; c++) {
            wmma::fragment<wmma::matrix_b, 16, 16, 16, __half, wmma::row_major> bf;
            wmma::load_matrix_sync(bf, &Wh[(ks * 16) * WH_S + cg * 32 + c * 16], WH_S);
            wmma::mma_sync(acc[c], af, bf, acc[c]);
        }
    }
    __syncthreads();   // all warps done reading Xh/Wh before Stg alias overwrite

    #pragma unroll
    for (int c = 0; c < 2; c++)
        wmma::store_matrix_sync(&Stg[(rg * 16) * ST_S + cg * 32 + c * 16], acc[c],
                                ST_S, wmma::mem_row_major);
    __syncthreads();

    // epilogue: scale by dis, convert to fp16, STG.128 (64 rows x 2 half-rows)
    if (tid < 128) {
        int r = tid >> 1, hsel = tid & 1;
        int gr = row0 + r;
        if (gr < N) {
            float d = dis_buf[gr];
            const float* src = &Stg[r * ST_S + hsel * 32];
            __half* dst = out + (size_t)gr * 64 + hsel * 32;
            #pragma unroll
            for (int c8 = 0; c8 < 4; c8++) {
                float4 u = *(const float4*)(src + c8 * 8);
                float4 v = *(const float4*)(src + c8 * 8 + 4);
                __half2 p0 = __float22half2_rn(make_float2(u.x * d, u.y * d));
                __half2 p1 = __float22half2_rn(make_float2(u.z * d, u.w * d));
                __half2 p2 = __float22half2_rn(make_float2(v.x * d, v.y * d));
                __half2 p3 = __float22half2_rn(make_float2(v.z * d, v.w * d));
                uint4 pk;
                pk.x = *(unsigned*)&p0;
                pk.y = *(unsigned*)&p1;
                pk.z = *(unsigned*)&p2;
                pk.w = *(unsigned*)&p3;
                *(uint4*)(dst + c8 * 8) = pk;
            }
        }
    }
}

// ---------------------------------------------------------------------------
// Pull aggregation: one warp per dst node. Half-warp (16 lanes x uint2 = 128B
// = one cache line) covers one edge's fp16 row. 16-edge unrolled main loop
// issues all 8 gathers before any accumulate -> 16 lines in flight per warp.
__device__ __forceinline__ float4 h4_to_f4(uint2 v) {
    __half2 a = *(__half2*)&v.x;
    __half2 b = *(__half2*)&v.y;
    float2 fa = __half22float2(a);
    float2 fb = __half22float2(b);
    return make_float4(fa.x, fa.y, fb.x, fb.y);
}
__device__ __forceinline__ void f4add(float4& a, float4 v) {
    a.x += v.x; a.y += v.y; a.z += v.z; a.w += v.w;
}

// OUTHALF: write fp16 h (intermediate layers). SPLIT: final fp32 mu/logvar.
template <bool RELU, bool SPLIT, bool OUTHALF>
__global__ void agg_kernel(const __half* __restrict__ g,
                           const float* __restrict__ ba,
                           const float* __restrict__ bb,
                           void* __restrict__ outv, int N)
{
    int warp = (int)((blockIdx.x * (unsigned)blockDim.x + threadIdx.x) >> 5);
    int lane = threadIdx.x & 31;
    if (warp >= N) return;
    int row  = warp;
    int half = lane >> 4;
    int li   = lane & 15;

    const uint2* gp = (const uint2*)g;   // 16 uint2 (64 halves) per row

    float4 a0 = make_float4(0.f, 0.f, 0.f, 0.f);
    float4 a1 = a0, a2 = a0, a3 = a0;
    if (half == 0) f4add(a0, h4_to_f4(gp[(size_t)row * 16 + li]));   // self-loop

    int beg = offs_buf[row];
    int end = offs_buf[row + 1];
    int e = beg;
    // 16-edge batches: all 8 gathers (per half) issued before any accumulate
    for (; e + 15 < end; e += 16) {
        int sA0 = csr_buf[e      + half];
        int sA1 = csr_buf[e + 2  + half];
        int sA2 = csr_buf[e + 4  + half];
        int sA3 = csr_buf[e + 6  + half];
        int sB0 = csr_buf[e + 8  + half];
        int sB1 = csr_buf[e + 10 + half];
        int sB2 = csr_buf[e + 12 + half];
        int sB3 = csr_buf[e + 14 + half];
        uint2 uA0 = gp[(size_t)sA0 * 16 + li];
        uint2 uA1 = gp[(size_t)sA1 * 16 + li];
        uint2 uA2 = gp[(size_t)sA2 * 16 + li];
        uint2 uA3 = gp[(size_t)sA3 * 16 + li];
        uint2 uB0 = gp[(size_t)sB0 * 16 + li];
        uint2 uB1 = gp[(size_t)sB1 * 16 + li];
        uint2 uB2 = gp[(size_t)sB2 * 16 + li];
        uint2 uB3 = gp[(size_t)sB3 * 16 + li];
        f4add(a0, h4_to_f4(uA0)); f4add(a1, h4_to_f4(uA1));
        f4add(a2, h4_to_f4(uA2)); f4add(a3, h4_to_f4(uA3));
        f4add(a0, h4_to_f4(uB0)); f4add(a1, h4_to_f4(uB1));
        f4add(a2, h4_to_f4(uB2)); f4add(a3, h4_to_f4(uB3));
    }
    for (; e + 7 < end; e += 8) {
        int s0 = csr_buf[e     + half];
        int s1 = csr_buf[e + 2 + half];
        int s2 = csr_buf[e + 4 + half];
        int s3 = csr_buf[e + 6 + half];
        uint2 u0 = gp[(size_t)s0 * 16 + li];
        uint2 u1 = gp[(size_t)s1 * 16 + li];
        uint2 u2 = gp[(size_t)s2 * 16 + li];
        uint2 u3 = gp[(size_t)s3 * 16 + li];
        f4add(a0, h4_to_f4(u0)); f4add(a1, h4_to_f4(u1));
        f4add(a2, h4_to_f4(u2)); f4add(a3, h4_to_f4(u3));
    }
    for (; e + 1 < end; e += 2) {
        int s = csr_buf[e + half];
        f4add(a0, h4_to_f4(gp[(size_t)s * 16 + li]));
    }
    if (e < end && half == 0) {
        f4add(a0, h4_to_f4(gp[(size_t)csr_buf[e] * 16 + li]));
    }
    a0.x += a1.x + a2.x + a3.x;
    a0.y += a1.y + a2.y + a3.y;
    a0.z += a1.z + a2.z + a3.z;
    a0.w += a1.w + a2.w + a3.w;

    a0.x += __shfl_xor_sync(0xffffffffu, a0.x, 16);
    a0.y += __shfl_xor_sync(0xffffffffu, a0.y, 16);
    a0.z += __shfl_xor_sync(0xffffffffu, a0.z, 16);
    a0.w += __shfl_xor_sync(0xffffffffu, a0.w, 16);

    if (half == 0) {
        float d = dis_buf[row];
        int c0 = 4 * li;
        float4 b4;
        if (SPLIT) {
            b4.x = (c0     < 32) ? ba[c0]     : bb[c0 - 32];
            b4.y = (c0 + 1 < 32) ? ba[c0 + 1] : bb[c0 + 1 - 32];
            b4.z = (c0 + 2 < 32) ? ba[c0 + 2] : bb[c0 + 2 - 32];
            b4.w = (c0 + 3 < 32) ? ba[c0 + 3] : bb[c0 + 3 - 32];
        } else {
            b4 = *(const float4*)(ba + c0);
        }
        float4 r;
        r.x = fmaf(d, a0.x, b4.x);
        r.y = fmaf(d, a0.y, b4.y);
        r.z = fmaf(d, a0.z, b4.z);
        r.w = fmaf(d, a0.w, b4.w);
        if (RELU) {
            r.x = fmaxf(r.x, 0.f); r.y = fmaxf(r.y, 0.f);
            r.z = fmaxf(r.z, 0.f); r.w = fmaxf(r.w, 0.f);
        }
        if (OUTHALF) {
            __half2 q0 = __float22half2_rn(make_float2(r.x, r.y));
            __half2 q1 = __float22half2_rn(make_float2(r.z, r.w));
            uint2 pk;
            pk.x = *(unsigned*)&q0;
            pk.y = *(unsigned*)&q1;
            ((uint2*)outv)[(size_t)row * 16 + li] = pk;
        } else if (SPLIT) {
            float* out = (float*)outv;
            if (li < 8) ((float4*)out)[(size_t)row * 8 + li] = r;                          // mu
            else        ((float4*)(out + (size_t)N * 32))[(size_t)row * 8 + (li - 8)] = r; // logvar
        } else {
            ((float4*)outv)[(size_t)row * 16 + li] = r;
        }
    }
}

// ---------------------------------------------------------------------------
extern "C" void kernel_launch(void* const* d_in, const int* in_sizes, int n_in,
                              void* d_out, int out_size)
{
    const float* x   = (const float*)d_in[0];
    const int*   ei  = (const int*)  d_in[1];
    const float* W1  = (const float*)d_in[2];
    const float* b1  = (const float*)d_in[3];
    const float* W2  = (const float*)d_in[4];
    const float* b2  = (const float*)d_in[5];
    const float* Wmu = (const float*)d_in[6];
    const float* bmu = (const float*)d_in[7];
    const float* Wlv = (const float*)d_in[8];
    const float* blv = (const float*)d_in[9];
    float* out = (float*)d_out;

    int N = in_sizes[0] / 128;
    int E = in_sizes[1] / 2;
    int nb = (N + SCAN_B - 1) / SCAN_B;

    __half* g = nullptr;
    __half* h = nullptr;
    __half* w1h = nullptr;
    __half* w2h = nullptr;
    __half* wch = nullptr;
    cudaGetSymbolAddress((void**)&g, g_buf);
    cudaGetSymbolAddress((void**)&h, h_buf);
    cudaGetSymbolAddress((void**)&w1h, w1h_buf);
    cudaGetSymbolAddress((void**)&w2h, w2h_buf);
    cudaGetSymbolAddress((void**)&wch, wch_buf);

    int gemm_grid = (N + 63) / 64;
    int agg_grid  = (N + 7) / 8;

    prep_kernel<<<(N + W_TASKS + 255) / 256, 256>>>(W1, W2, Wmu, Wlv, N);        // idx 0
    count_deg_kernel<<<(E + 255) / 256, 256>>>(ei, E);                           // idx 1
    reduce_deg_kernel<<<nb, SCAN_B>>>(N);                                        // idx 2 (also dis)
    gemm_wmma_kernel<128, false><<<gemm_grid, 256>>>(x, w1h, g, N);              // idx 3 (profiled)
    scan_sums_kernel<<<1, 128>>>(nb, N);
    scan_deg_kernel<<<nb, SCAN_B>>>(N);
    fill_csr_kernel<<<(E + 255) / 256, 256>>>(ei, E);

    agg_kernel<true, false, true><<<agg_grid, 256>>>(g, b1, nullptr, h, N);

    gemm_wmma_kernel<64, true><<<gemm_grid, 256>>>(h, w2h, g, N);
    agg_kernel<true, false, true><<<agg_grid, 256>>>(g, b2, nullptr, h, N);

    gemm_wmma_kernel<64, true><<<gemm_grid, 256>>>(h, wch, g, N);
    agg_kernel<false, true, false><<<agg_grid, 256>>>(g, bmu, blv, out, N);
}